// round 17
// baseline (speedup 1.0000x reference)
#include <cuda_runtime.h>
#include <math.h>

#define N_ 4096
#define HD 32
#define KNUM 2048
#define SCALE 0.17677669529663687f

// scratch (__device__ globals: allocation-free rule)
__device__ float    g_qkv[768 * N_];
__device__ float    g_q[8 * N_ * HD];              // [h][n][d]
__device__ float    g_kT[8 * HD * N_];             // [h][d][n]  (transposed K)
__device__ float    g_v[8 * N_ * HD];              // [h][n][d]
__device__ unsigned g_S[(size_t)8 * N_ * N_];      // u-mapped scores [h][row][key], 512MB
__device__ unsigned g_T[8 * N_];                   // per-row k-th threshold (u-mapped)
__device__ float    g_Inv[8 * N_];                 // per-row 1/sum(exp)
__device__ float    g_attn[256 * N_];
__device__ float    g_proj[256 * N_];

__device__ __forceinline__ unsigned umap_score(float a) {
    float s = fminf(fmaxf(a * SCALE, -32.f), 32.f);
    unsigned bb = __float_as_uint(s);
    return (bb & 0x80000000u) ? ~bb : (bb | 0x80000000u);
}

__device__ __forceinline__ float udecode_p(unsigned u, unsigned T) {
    if (u < T) return 0.f;
    unsigned bb = (u & 0x80000000u) ? (u & 0x7FFFFFFFu) : ~u;
    return __expf(__uint_as_float(bb));
}

#define GETC(v4, kk) ((kk) == 0 ? (v4).x : (kk) == 1 ? (v4).y : (kk) == 2 ? (v4).z : (v4).w)

// ---------------- SGEMM: C[M][4096] = A[M][256] * B[256][4096] ----------------
__global__ void __launch_bounds__(256) k_sgemm(const float* __restrict__ A,
                                               const float* __restrict__ Bx, int mode) {
    const float* B = mode ? (const float*)g_attn : Bx;
    float* C = mode ? g_proj : g_qkv;
    __shared__ float As[64][17];
    __shared__ float Bs[16][128];
    int t = threadIdx.x;
    int bm = blockIdx.y * 64, bn = blockIdx.x * 128;
    int tr = t >> 4, tc = t & 15;
    int arow = t >> 2, akk = (t & 3) * 4;
    int brow = t >> 4, bcol = (t & 15) * 8;
    float acc[4][8];
#pragma unroll
    for (int i = 0; i < 4; i++)
#pragma unroll
        for (int j = 0; j < 8; j++) acc[i][j] = 0.f;
    for (int k0 = 0; k0 < 256; k0 += 16) {
        float4 a4 = *(const float4*)&A[(bm + arow) * 256 + k0 + akk];
        float4 b0 = *(const float4*)&B[(size_t)(k0 + brow) * N_ + bn + bcol];
        float4 b1 = *(const float4*)&B[(size_t)(k0 + brow) * N_ + bn + bcol + 4];
        __syncthreads();
        As[arow][akk + 0] = a4.x; As[arow][akk + 1] = a4.y;
        As[arow][akk + 2] = a4.z; As[arow][akk + 3] = a4.w;
        *(float4*)&Bs[brow][bcol] = b0;
        *(float4*)&Bs[brow][bcol + 4] = b1;
        __syncthreads();
#pragma unroll
        for (int k = 0; k < 16; k++) {
            float4 bv0 = *(const float4*)&Bs[k][tc * 4];
            float4 bv1 = *(const float4*)&Bs[k][64 + tc * 4];
#pragma unroll
            for (int i = 0; i < 4; i++) {
                float a = As[tr * 4 + i][k];
                acc[i][0] += a * bv0.x; acc[i][1] += a * bv0.y;
                acc[i][2] += a * bv0.z; acc[i][3] += a * bv0.w;
                acc[i][4] += a * bv1.x; acc[i][5] += a * bv1.y;
                acc[i][6] += a * bv1.z; acc[i][7] += a * bv1.w;
            }
        }
    }
#pragma unroll
    for (int i = 0; i < 4; i++) {
        size_t row = bm + tr * 4 + i;
        *(float4*)&C[row * N_ + bn + tc * 4] =
            make_float4(acc[i][0], acc[i][1], acc[i][2], acc[i][3]);
        *(float4*)&C[row * N_ + bn + 64 + tc * 4] =
            make_float4(acc[i][4], acc[i][5], acc[i][6], acc[i][7]);
    }
}

// ---- transpose [3C][N]: q -> [h][n][d] (l2norm), k -> [h][d][n] (l2norm), v -> [h][n][d]
__global__ void __launch_bounds__(256) k_prep() {
    int which = blockIdx.y;                         // 0=q 1=k 2=v
    int idx = blockIdx.x * 256 + threadIdx.x;       // h*4096+n
    int h = idx >> 12, n = idx & 4095;
    const float* src = g_qkv + (size_t)(which * 256 + h * 32) * N_ + n;
    float s[32], ss = 0.f;
#pragma unroll
    for (int d = 0; d < 32; d++) { s[d] = src[(size_t)d * N_]; ss += s[d] * s[d]; }
    float inv = 1.f;
    if (which < 2) inv = 1.f / fmaxf(sqrtf(ss), 1e-12f);
    if (which == 1) {           // K: store transposed [h][d][n]
#pragma unroll
        for (int d = 0; d < 32; d++)
            g_kT[(size_t)(h * 32 + d) * N_ + n] = s[d] * inv;
    } else {
        float* dst = (which == 0 ? g_q : g_v) + (size_t)idx * 32;
#pragma unroll
        for (int d = 0; d < 32; d++) dst[d] = s[d] * inv;
    }
}

// ---------------- QK GEMM: S[h][row][key] = umap(clamp(q.k * scale)) ----------------
__global__ void __launch_bounds__(256) k_qk() {
    __shared__ float Qs[64 * 36];
    __shared__ float Ks[32 * 132];
    int t = threadIdx.x;
    int h = blockIdx.z;
    int i0 = blockIdx.y * 64;
    int j0 = blockIdx.x * 128;

    const float4* qsrc = (const float4*)(g_q + ((size_t)h * N_ + i0) * HD);
#pragma unroll
    for (int q = 0; q < 2; q++) {
        int idx = q * 256 + t;
        int row = idx >> 3, d4 = idx & 7;
        *(float4*)&Qs[row * 36 + d4 * 4] = qsrc[idx];
    }
#pragma unroll
    for (int q = 0; q < 4; q++) {
        int idx = q * 256 + t;
        int d = idx >> 5, k4 = idx & 31;
        *(float4*)&Ks[d * 132 + k4 * 4] =
            *(const float4*)(g_kT + (size_t)(h * HD + d) * N_ + j0 + k4 * 4);
    }
    __syncthreads();

    int tr = t >> 4, tc = t & 15;
    float acc[4][8];
#pragma unroll
    for (int i = 0; i < 4; i++)
#pragma unroll
        for (int j = 0; j < 8; j++) acc[i][j] = 0.f;

#pragma unroll
    for (int dc = 0; dc < 8; dc++) {
        float4 b0[4], b1[4];
#pragma unroll
        for (int j = 0; j < 4; j++) {
            b0[j] = *(float4*)&Ks[(dc * 4 + j) * 132 + tc * 4];
            b1[j] = *(float4*)&Ks[(dc * 4 + j) * 132 + 64 + tc * 4];
        }
#pragma unroll
        for (int i = 0; i < 4; i++) {
            float4 a = *(float4*)&Qs[(tr * 4 + i) * 36 + dc * 4];
#pragma unroll
            for (int kk = 0; kk < 4; kk++) {
                acc[i][kk]     += a.x * GETC(b0[0], kk) + a.y * GETC(b0[1], kk)
                                + a.z * GETC(b0[2], kk) + a.w * GETC(b0[3], kk);
                acc[i][4 + kk] += a.x * GETC(b1[0], kk) + a.y * GETC(b1[1], kk)
                                + a.z * GETC(b1[2], kk) + a.w * GETC(b1[3], kk);
            }
        }
    }

#pragma unroll
    for (int i = 0; i < 4; i++) {
        int row = i0 + tr * 4 + i;
        size_t base = ((size_t)h * N_ + row) * N_ + j0;
        uint4 o0, o1;
        o0.x = umap_score(acc[i][0]); o0.y = umap_score(acc[i][1]);
        o0.z = umap_score(acc[i][2]); o0.w = umap_score(acc[i][3]);
        o1.x = umap_score(acc[i][4]); o1.y = umap_score(acc[i][5]);
        o1.z = umap_score(acc[i][6]); o1.w = umap_score(acc[i][7]);
        *(uint4*)&g_S[base + tc * 4] = o0;
        *(uint4*)&g_S[base + 64 + tc * 4] = o1;
    }
}

// ---------------- per-row select: exact k-th threshold + exp-sum ----------------
// Register-resident: row lives in uu[16] per thread. Pass A: 2048-bin histogram
// (bits 31:21). Then collect prefix-matching candidates (tiny near the median)
// into smem and finish low-21-bit selection with a warp bitwise select.
// Fallback (>2048 candidates): block-wide bitwise select from registers.
__global__ void __launch_bounds__(256) k_sel() {
    __shared__ int hist[2048];
    __shared__ unsigned cand[2048];
    __shared__ unsigned s_pref, s_T;
    __shared__ int s_want, s_pos, s_cb;
    __shared__ float s_red[8];
    __shared__ int s_wsum[8];
    int b = blockIdx.x;                  // h*4096 + row
    int t = threadIdx.x, l = t & 31, w = t >> 5;

#pragma unroll
    for (int q = 0; q < 8; q++) hist[q * 256 + t] = 0;
    if (t == 0) s_pos = 0;
    __syncthreads();

    const uint4* src = (const uint4*)(g_S + (size_t)b * N_);
    unsigned uu[16];
#pragma unroll
    for (int q = 0; q < 4; q++) {
        uint4 v = src[q * 256 + t];
        uu[q * 4 + 0] = v.x; uu[q * 4 + 1] = v.y;
        uu[q * 4 + 2] = v.z; uu[q * 4 + 3] = v.w;
    }
#pragma unroll
    for (int x = 0; x < 16; x++) atomicAdd(&hist[uu[x] >> 21], 1);
    __syncthreads();

    // ---- Pass A: block-wide descending scan over 2048 bins
    {
        int base = 2047 - t * 8;
        int cnt[8]; int local = 0;
#pragma unroll
        for (int i = 0; i < 8; i++) { cnt[i] = hist[base - i]; local += cnt[i]; }
        int pre = local;
#pragma unroll
        for (int o = 1; o < 32; o <<= 1) {
            int x = __shfl_up_sync(0xffffffffu, pre, o);
            if (l >= o) pre += x;
        }
        if (l == 31) s_wsum[w] = pre;
        __syncthreads();
        int woff = 0;
        for (int i = 0; i < w; i++) woff += s_wsum[i];
        int cum_before = woff + pre - local;
        if (cum_before < KNUM && cum_before + local >= KNUM) {
            int rem = KNUM - cum_before, c = 0;
#pragma unroll
            for (int i = 0; i < 8; i++) {
                if (c + cnt[i] >= rem) {
                    s_pref = (unsigned)(base - i);
                    s_want = rem - c;
                    break;
                }
                c += cnt[i];
            }
        }
    }
    __syncthreads();
    unsigned pref = s_pref;
    int want0 = s_want;

    // ---- collect candidates (from registers)
#pragma unroll
    for (int x = 0; x < 16; x++) {
        if ((uu[x] >> 21) == pref) {
            int p = atomicAdd(&s_pos, 1);
            if (p < 2048) cand[p] = uu[x];
        }
    }
    __syncthreads();
    int cnt = s_pos;

    if (cnt <= 2048) {
        if (w == 0) {                    // warp bitwise select over low 21 bits
            unsigned cur = 0; int want = want0;
            for (int bb = 20; bb >= 0; bb--) {
                int cb = 0;
                for (int i = l; i < cnt; i += 32) {
                    unsigned v = cand[i] & 0x1FFFFFu;
                    if ((v >> bb) == ((cur >> bb) | 1u)) cb++;
                }
#pragma unroll
                for (int o = 16; o; o >>= 1) cb += __shfl_xor_sync(0xffffffffu, cb, o);
                if (cb >= want) cur |= (1u << bb); else want -= cb;
            }
            if (l == 0) s_T = (pref << 21) | cur;
        }
        __syncthreads();
    } else {                             // degenerate fallback, exact
        unsigned cur = 0; int want = want0;
        for (int bb = 20; bb >= 0; bb--) {
            if (t == 0) s_cb = 0;
            __syncthreads();
            int local = 0;
#pragma unroll
            for (int x = 0; x < 16; x++) {
                unsigned u = uu[x];
                if ((u >> 21) == pref) {
                    unsigned v = u & 0x1FFFFFu;
                    if ((v >> bb) == ((cur >> bb) | 1u)) local++;
                }
            }
#pragma unroll
            for (int o = 16; o; o >>= 1) local += __shfl_xor_sync(0xffffffffu, local, o);
            if (l == 0) atomicAdd(&s_cb, local);
            __syncthreads();
            int cb = s_cb;
            if (cb >= want) cur |= (1u << bb); else want -= cb;
            __syncthreads();
        }
        if (t == 0) s_T = (pref << 21) | cur;
        __syncthreads();
    }
    unsigned T = s_T;

    // ---- exp-sum over kept elements (from registers)
    float sum = 0.f;
#pragma unroll
    for (int x = 0; x < 16; x++) {
        unsigned u = uu[x];
        if (u >= T) {
            unsigned bb = (u & 0x80000000u) ? (u & 0x7FFFFFFFu) : ~u;
            sum += __expf(__uint_as_float(bb));
        }
    }
#pragma unroll
    for (int o = 16; o; o >>= 1) sum += __shfl_xor_sync(0xffffffffu, sum, o);
    if (l == 0) s_red[w] = sum;
    __syncthreads();
    if (t == 0) {
        float tot = 0.f;
#pragma unroll
        for (int i = 0; i < 8; i++) tot += s_red[i];
        g_T[b] = T;
        g_Inv[b] = 1.f / tot;
    }
}

// ---------------- AV GEMM: out = softmax(P) * V ----------------
// 128 rows x 32 dims per CTA; 64-key chunks, double-buffered P/V smem with
// register staging: decode+STS chunk c, one barrier, prefetch c+1, compute c.
#define AVP0 0                           // P buf0 [128][68]
#define AVP1 8704                        // P buf1
#define AVV0 17408                       // V buf0 [64][36]
#define AVV1 19712                       // V buf1
#define AVT_OFF 22016                    // T [128] (uint)
#define AVI_OFF 22144                    // Inv [128]
#define AV_TOT  22272                    // floats = 89088 bytes (2 CTAs/SM)

__global__ void __launch_bounds__(256, 2) k_av() {
    extern __shared__ float avs[];
    unsigned* sT   = (unsigned*)(avs + AVT_OFF);
    float*    sInv = avs + AVI_OFF;

    int t = threadIdx.x;
    int h = blockIdx.y;
    int r0 = blockIdx.x * 128;
    int ks = t >> 7;                     // key half (0/1) of each 64-key chunk
    int u7 = t & 127;
    int w4 = u7 >> 5;
    int lane = u7 & 31;
    int row_lo = lane & 3;
    int dg = lane >> 2;

    if (t < 128) {
        sT[t]   = g_T[h * N_ + r0 + t];
        sInv[t] = g_Inv[h * N_ + r0 + t];
    }
    __syncthreads();

    float acc[8][4];
#pragma unroll
    for (int i = 0; i < 8; i++)
#pragma unroll
        for (int d = 0; d < 4; d++) acc[i][d] = 0.f;

    const unsigned* Sbase = g_S + ((size_t)h * N_ + r0) * N_;
    const float4* Vsrc = (const float4*)(g_v + (size_t)h * N_ * HD);

    // register staging for one 64-key chunk
    uint4  sA[8];                        // 128x64 uints / 256 thr = 8 uint4
    float4 vA[2];                        // 64x32 floats / 256 thr = 2 float4

    // prologue: load chunk 0
#pragma unroll
    for (int q = 0; q < 8; q++) {
        int idx = q * 256 + t;
        int row = idx >> 4, k4 = idx & 15;
        sA[q] = *(const uint4*)&Sbase[(size_t)row * N_ + k4 * 4];
    }
#pragma unroll
    for (int q = 0; q < 2; q++) {
        int idx = q * 256 + t;
        vA[q] = Vsrc[(size_t)(idx >> 3) * 8 + (idx & 7)];
    }

    for (int c = 0; c < 64; c++) {
        float* P = avs + ((c & 1) ? AVP1 : AVP0);
        float* V = avs + ((c & 1) ? AVV1 : AVV0);
        // decode + store chunk c from registers
#pragma unroll
        for (int q = 0; q < 8; q++) {
            int idx = q * 256 + t;
            int row = idx >> 4, k4 = idx & 15;
            unsigned Tr = sT[row];
            float4 p4;
            p4.x = udecode_p(sA[q].x, Tr);
            p4.y = udecode_p(sA[q].y, Tr);
            p4.z = udecode_p(sA[q].z, Tr);
            p4.w = udecode_p(sA[q].w, Tr);
            *(float4*)&P[row * 68 + k4 * 4] = p4;
        }
#pragma unroll
        for (int q = 0; q < 2; q++) {
            int idx = q * 256 + t;
            *(float4*)&V[(idx >> 3) * 36 + (idx & 7) * 4] = vA[q];
        }
        __syncthreads();
        // prefetch chunk c+1 (latency hidden under compute)
        if (c + 1 < 64) {
            int c0 = (c + 1) * 64;
#pragma unroll
            for (int q = 0; q < 8; q++) {
                int idx = q * 256 + t;
                int row = idx >> 4, k4 = idx & 15;
                sA[q] = *(const uint4*)&Sbase[(size_t)row * N_ + c0 + k4 * 4];
            }
#pragma unroll
            for (int q = 0; q < 2; q++) {
                int idx = q * 256 + t;
                vA[q] = Vsrc[(size_t)(c0 + (idx >> 3)) * 8 + (idx & 7)];
            }
        }
        // compute chunk c: own 32-key half; 8 rows x 4 dims per thread
        int kb = ks * 32;
        for (int m = 0; m < 32; m += 4) {
            float4 v0 = *(float4*)&V[(kb + m + 0) * 36 + dg * 4];
            float4 v1 = *(float4*)&V[(kb + m + 1) * 36 + dg * 4];
            float4 v2 = *(float4*)&V[(kb + m + 2) * 36 + dg * 4];
            float4 v3 = *(float4*)&V[(kb + m + 3) * 36 + dg * 4];
#pragma unroll
            for (int i = 0; i < 8; i++) {
                int R = w4 * 32 + row_lo + 4 * i;
                float4 p = *(float4*)&P[R * 68 + kb + m];
                acc[i][0] += p.x * v0.x + p.y * v1.x + p.z * v2.x + p.w * v3.x;
                acc[i][1] += p.x * v0.y + p.y * v1.y + p.z * v2.y + p.w * v3.y;
                acc[i][2] += p.x * v0.z + p.y * v1.z + p.z * v2.z + p.w * v3.z;
                acc[i][3] += p.x * v0.w + p.y * v1.w + p.z * v2.w + p.w * v3.w;
            }
        }
    }

    // reduce the two key halves via smem (reuse P buffer region; stride 36)
    __syncthreads();
    float* red = avs;                    // 128 x 36
    if (ks == 1) {
#pragma unroll
        for (int i = 0; i < 8; i++) {
            int R = w4 * 32 + row_lo + 4 * i;
            *(float4*)&red[R * 36 + dg * 4] =
                make_float4(acc[i][0], acc[i][1], acc[i][2], acc[i][3]);
        }
    }
    __syncthreads();
    if (ks == 0) {
#pragma unroll
        for (int i = 0; i < 8; i++) {
            int R = w4 * 32 + row_lo + 4 * i;
            float4 o = *(float4*)&red[R * 36 + dg * 4];
            float inv = sInv[R];
            int row = r0 + R;
            g_attn[(size_t)(h * 32 + dg * 4 + 0) * N_ + row] = (acc[i][0] + o.x) * inv;
            g_attn[(size_t)(h * 32 + dg * 4 + 1) * N_ + row] = (acc[i][1] + o.y) * inv;
            g_attn[(size_t)(h * 32 + dg * 4 + 2) * N_ + row] = (acc[i][2] + o.z) * inv;
            g_attn[(size_t)(h * 32 + dg * 4 + 3) * N_ + row] = (acc[i][3] + o.w) * inv;
        }
    }
}

// ---------------- GroupNorm(32 groups) ----------------
__global__ void __launch_bounds__(256) k_gn(const float* __restrict__ gamma,
                                            const float* __restrict__ beta,
                                            float* __restrict__ out) {
    __shared__ float rs[2][8];
    int g = blockIdx.x, t = threadIdx.x;
    const float* src = g_proj + (size_t)g * 8 * N_;
    float sum = 0.f, sq = 0.f;
    for (int i = t; i < 8 * N_; i += 256) { float v = src[i]; sum += v; sq += v * v; }
#pragma unroll
    for (int o = 16; o; o >>= 1) {
        sum += __shfl_xor_sync(0xffffffffu, sum, o);
        sq  += __shfl_xor_sync(0xffffffffu, sq, o);
    }
    if ((t & 31) == 0) { rs[0][t >> 5] = sum; rs[1][t >> 5] = sq; }
    __syncthreads();
    if (t < 32) {
        float a = (t < 8) ? rs[0][t] : 0.f;
        float b = (t < 8) ? rs[1][t] : 0.f;
#pragma unroll
        for (int o = 4; o; o >>= 1) {
            a += __shfl_xor_sync(0xffffffffu, a, o);
            b += __shfl_xor_sync(0xffffffffu, b, o);
        }
        if (t == 0) { rs[0][0] = a; rs[1][0] = b; }
    }
    __syncthreads();
    float inv_m = 1.f / (8.f * N_);
    float mean = rs[0][0] * inv_m;
    float var = rs[1][0] * inv_m - mean * mean;
    float rstd = rsqrtf(var + 1e-6f);
    for (int i = t; i < 8 * N_; i += 256) {
        int c = g * 8 + (i >> 12);
        out[(size_t)g * 8 * N_ + i] = (src[i] - mean) * rstd * gamma[c] + beta[c];
    }
}

extern "C" void kernel_launch(void* const* d_in, const int* in_sizes, int n_in,
                              void* d_out, int out_size) {
    (void)in_sizes; (void)n_in; (void)out_size;
    const float* x      = (const float*)d_in[0];
    const float* w_qkv  = (const float*)d_in[1];
    const float* w_proj = (const float*)d_in[2];
    const float* gamma  = (const float*)d_in[3];
    const float* beta   = (const float*)d_in[4];
    float* out = (float*)d_out;

    cudaFuncSetAttribute(k_av, cudaFuncAttributeMaxDynamicSharedMemorySize,
                         AV_TOT * (int)sizeof(float));

    // harness issues 2 internal launches first; ncu -s 5 captures global
    // index 5 = my index 3 -> k_sel (verifying this round's sel rewrite).
    k_sgemm<<<dim3(32, 12), 256>>>(w_qkv, x, 0);               // my 0: qkv
    k_prep<<<dim3(128, 3), 256>>>();                            // my 1
    k_qk<<<dim3(32, 64, 8), 256>>>();                           // my 2
    k_sel<<<32768, 256>>>();                                    // my 3 (profiled)
    k_av<<<dim3(32, 8), 256, AV_TOT * sizeof(float)>>>();       // my 4
    k_sgemm<<<dim3(32, 4), 256>>>(w_proj, nullptr, 1);          // my 5: proj
    k_gn<<<32, 256>>>(gamma, beta, out);                        // my 6
}